// round 8
// baseline (speedup 1.0000x reference)
#include <cuda_runtime.h>
#include <math.h>
#include <stdint.h>

// ---------------- problem constants ----------------
#define BB      64
#define NP      377
#define NROWS   (BB * NP)        // 24128 = 377 * 64
#define CIN     384
#define HID     128
#define H2X     256
#define SD      16
#define KNEI    6
#define PIN_DIM (SD * (KNEI + 1)) // 112
#define NSTEPS  16
#define FH      37
#define DHH     518

// pads chosen so all MMA fragment LDS are bank-conflict-free
#define APAD 72     // As rows [16][72]
#define WPAD 136    // Ws rows [16][136]

// gemm_tc dynamic smem (floats)
#define G_ASH 0                     // [2][16][72]  = 2304
#define G_ASL 2304
#define G_WSH 4608                  // [2][16][136] = 4352
#define G_WSL 8960
#define G_TOTAL_F 13312
#define G_TOTAL_B (G_TOTAL_F * 4)   // 53248

// fused_step dynamic smem (floats)
#define F_ASH 0
#define F_ASL 2304
#define F_WSH 4608
#define F_WSL 8960
#define F_HSH 13312                 // [128][72] = 9216
#define F_HSL 22528
#define F_B1  31744
#define F_B2  31872
#define F_B3  32000
#define F_TOTAL_F 32016
#define F_TOTAL_B (F_TOTAL_F * 4)   // 128064

// ---------------- tf32 helpers ----------------------------------------------
__device__ __forceinline__ float tf32_rnd(float x) {
    uint32_t r;
    asm("cvt.rna.tf32.f32 %0, %1;" : "=r"(r) : "f"(x));
    return __uint_as_float(r);
}
__device__ __forceinline__ void split_tf32(float x, float& hi, float& lo) {
    hi = tf32_rnd(x);
    lo = tf32_rnd(x - hi);
}
__device__ __forceinline__ void mma8(float* d, const uint32_t* a, const uint32_t* b) {
    asm volatile(
        "mma.sync.aligned.m16n8k8.row.col.f32.tf32.tf32.f32 "
        "{%0,%1,%2,%3}, {%4,%5,%6,%7}, {%8,%9}, {%0,%1,%2,%3};"
        : "+f"(d[0]), "+f"(d[1]), "+f"(d[2]), "+f"(d[3])
        : "r"(a[0]), "r"(a[1]), "r"(a[2]), "r"(a[3]), "r"(b[0]), "r"(b[1]));
}
__device__ __forceinline__ uint32_t fbits(float x) { return __float_as_uint(x); }

// A fragment (m16k8): a0=[r][c], a1=[r+8][c], a2=[r][c+4], a3=[r+8][c+4]
__device__ __forceinline__ void load_afrag(uint32_t a[4], const float* As /*[16][APAD]*/,
                                           int kb, int mb, int r, int cc) {
    const float* p0 = As + (kb + cc) * APAD + mb + r;
    const float* p1 = As + (kb + cc + 4) * APAD + mb + r;
    a[0] = fbits(p0[0]);
    a[1] = fbits(p0[8]);
    a[2] = fbits(p1[0]);
    a[3] = fbits(p1[8]);
}
// B fragment (k8n8 col): b0=[k=cc][n=r], b1=[k=cc+4][n=r]
__device__ __forceinline__ void load_bfrag(uint32_t b[2], const float* Ws /*[16][WPAD]*/,
                                           int kb, int nb, int r, int cc) {
    b[0] = fbits(Ws[(kb + cc) * WPAD + nb + r]);
    b[1] = fbits(Ws[(kb + cc + 4) * WPAD + nb + r]);
}

// one k8 sub-step for a 16x32 warp tile (4 n-tiles), 3xTF32
__device__ __forceinline__ void warp_k8(float d[4][4],
                                        const float* AsH, const float* AsL,
                                        const float* WsH, const float* WsL,
                                        int kb, int mb, int nbase, int r, int cc) {
    uint32_t ahi[4], alo[4];
    load_afrag(ahi, AsH, kb, mb, r, cc);
    load_afrag(alo, AsL, kb, mb, r, cc);
#pragma unroll
    for (int nt = 0; nt < 4; nt++) {
        uint32_t bh[2], bl[2];
        load_bfrag(bh, WsH, kb, nbase + 8 * nt, r, cc);
        load_bfrag(bl, WsL, kb, nbase + 8 * nt, r, cc);
        mma8(d[nt], alo, bh);
        mma8(d[nt], ahi, bl);
        mma8(d[nt], ahi, bh);
    }
}

// ---------------- scratch ----------------------------------------------------
__device__ float g_Fs[(size_t)NROWS * CIN];
__device__ float g_dep[NROWS];
__device__ float g_bufA[(size_t)NROWS * H2X];
__device__ float g_bufB[(size_t)NROWS * HID];
__device__ float g_init[(size_t)NROWS * SD];
__device__ float g_state[(size_t)NROWS * SD];
__device__ float g_pin[(size_t)NROWS * PIN_DIM];

// ---------------- feature bilinear sampling ----------------------------------
__global__ void sample_feat_kernel(const float* __restrict__ feat,
                                   const float* __restrict__ sx,
                                   const float* __restrict__ sy) {
    int row = blockIdx.x;
    int b = row / NP, n = row % NP;
    float gx = sx[n], gy = sy[n];

    float ix = fminf(fmaxf((gx + 1.0f) * 0.5f * (float)(FH - 1), 0.0f), (float)(FH - 1));
    float iy = fminf(fmaxf((gy + 1.0f) * 0.5f * (float)(FH - 1), 0.0f), (float)(FH - 1));
    int x0 = (int)floorf(ix), y0 = (int)floorf(iy);
    int x1 = min(x0 + 1, FH - 1), y1 = min(y0 + 1, FH - 1);
    float wx = ix - (float)x0, wy = iy - (float)y0;
    float w00 = (1.0f - wx) * (1.0f - wy);
    float w01 = wx * (1.0f - wy);
    float w10 = (1.0f - wx) * wy;
    float w11 = wx * wy;

    const float* fb = feat + (size_t)b * CIN * FH * FH;
    for (int c = threadIdx.x; c < CIN; c += blockDim.x) {
        const float* p = fb + (size_t)c * FH * FH;
        float v = p[y0 * FH + x0] * w00 + p[y0 * FH + x1] * w01 +
                  p[y1 * FH + x0] * w10 + p[y1 * FH + x1] * w11;
        g_Fs[(size_t)row * CIN + c] = v;
    }
}

// ---------------- depth bilinear sampling ------------------------------------
__global__ void sample_depth_kernel(const float* __restrict__ depth,
                                    const float* __restrict__ sx,
                                    const float* __restrict__ sy) {
    int row = blockIdx.x * blockDim.x + threadIdx.x;
    if (row >= NROWS) return;
    int b = row / NP, n = row % NP;
    float gx = sx[n], gy = sy[n];
    float jx = fminf(fmaxf((gx + 1.0f) * 0.5f * (float)(DHH - 1), 0.0f), (float)(DHH - 1));
    float jy = fminf(fmaxf((gy + 1.0f) * 0.5f * (float)(DHH - 1), 0.0f), (float)(DHH - 1));
    int a0 = (int)floorf(jx), c0 = (int)floorf(jy);
    int a1 = min(a0 + 1, DHH - 1), c1 = min(c0 + 1, DHH - 1);
    float ux = jx - (float)a0, uy = jy - (float)c0;
    const float* dp = depth + (size_t)b * DHH * DHH;
    float v = dp[c0 * DHH + a0] * (1.0f - ux) * (1.0f - uy) +
              dp[c0 * DHH + a1] * ux * (1.0f - uy) +
              dp[c1 * DHH + a0] * (1.0f - ux) * uy +
              dp[c1 * DHH + a1] * ux * uy;
    g_dep[row] = v;
}

// ---------------- tensor-core 64x128 GEMM (relu epilogue) --------------------
// 512 threads. warp: wm = warp>>2 (m-tile 16 rows), wn = warp&3 (32 cols).
__global__ void __launch_bounds__(512, 2)
gemm_tc(const float* __restrict__ A, const float* __restrict__ W,
        const float* __restrict__ bias, float* __restrict__ C,
        int K, int N) {
    extern __shared__ float dyn[];
    float* AsH = dyn + G_ASH;   // [2][16][APAD]
    float* AsL = dyn + G_ASL;
    float* WsH = dyn + G_WSH;   // [2][16][WPAD]
    float* WsL = dyn + G_WSL;

    int m0 = blockIdx.x * 64;
    int n0 = blockIdx.y * 128;
    int tid = threadIdx.x;
    int warp = tid >> 5, lane = tid & 31;
    int wm = warp >> 2, wn = warp & 3;
    int mb = 16 * wm, nbase = 32 * wn;
    int r = lane >> 2, cc = lane & 3;

    // loaders
    int am = tid >> 3;            // 0..63
    int aq = (tid & 7) * 2;       // 0..14
    int wk = tid >> 5;            // 0..15
    int wn4 = (tid & 31) * 4;

    float d[4][4];
#pragma unroll
    for (int i = 0; i < 4; i++)
#pragma unroll
        for (int j = 0; j < 4; j++) d[i][j] = 0.0f;

    // preload tile 0
    {
        float2 v = *reinterpret_cast<const float2*>(&A[(size_t)(m0 + am) * K + aq]);
        float h, l;
        split_tf32(v.x, h, l);
        AsH[aq * APAD + am] = h; AsL[aq * APAD + am] = l;
        split_tf32(v.y, h, l);
        AsH[(aq + 1) * APAD + am] = h; AsL[(aq + 1) * APAD + am] = l;

        float4 w = *reinterpret_cast<const float4*>(&W[(size_t)wk * N + n0 + wn4]);
        float4 wh, wl;
        split_tf32(w.x, wh.x, wl.x); split_tf32(w.y, wh.y, wl.y);
        split_tf32(w.z, wh.z, wl.z); split_tf32(w.w, wh.w, wl.w);
        *reinterpret_cast<float4*>(&WsH[wk * WPAD + wn4]) = wh;
        *reinterpret_cast<float4*>(&WsL[wk * WPAD + wn4]) = wl;
    }
    __syncthreads();

    int KT = K >> 4;
    int p = 0;
    const int ASTRIDE = 16 * APAD, WSTRIDE = 16 * WPAD;
    for (int t = 0; t < KT; t++) {
        float2 pa;
        float4 pw;
        bool has = (t + 1 < KT);
        if (has) {
            int k0 = (t + 1) << 4;
            pa = *reinterpret_cast<const float2*>(&A[(size_t)(m0 + am) * K + k0 + aq]);
            pw = *reinterpret_cast<const float4*>(&W[(size_t)(k0 + wk) * N + n0 + wn4]);
        }

        const float* ash = AsH + p * ASTRIDE;
        const float* asl = AsL + p * ASTRIDE;
        const float* wsh = WsH + p * WSTRIDE;
        const float* wsl = WsL + p * WSTRIDE;
        warp_k8(d, ash, asl, wsh, wsl, 0, mb, nbase, r, cc);
        warp_k8(d, ash, asl, wsh, wsl, 8, mb, nbase, r, cc);

        if (has) {
            int q = p ^ 1;
            float h, l;
            split_tf32(pa.x, h, l);
            AsH[q * ASTRIDE + aq * APAD + am] = h; AsL[q * ASTRIDE + aq * APAD + am] = l;
            split_tf32(pa.y, h, l);
            AsH[q * ASTRIDE + (aq + 1) * APAD + am] = h; AsL[q * ASTRIDE + (aq + 1) * APAD + am] = l;
            float4 wh, wl;
            split_tf32(pw.x, wh.x, wl.x); split_tf32(pw.y, wh.y, wl.y);
            split_tf32(pw.z, wh.z, wl.z); split_tf32(pw.w, wh.w, wl.w);
            *reinterpret_cast<float4*>(&WsH[q * WSTRIDE + wk * WPAD + wn4]) = wh;
            *reinterpret_cast<float4*>(&WsL[q * WSTRIDE + wk * WPAD + wn4]) = wl;
        }
        __syncthreads();
        p ^= 1;
    }

    // epilogue: bias + relu, float2 stores
    int row0 = m0 + mb + r;
#pragma unroll
    for (int nt = 0; nt < 4; nt++) {
        int col = n0 + nbase + 8 * nt + 2 * cc;
        float b0 = bias[col], b1 = bias[col + 1];
        float v0 = fmaxf(d[nt][0] + b0, 0.0f);
        float v1 = fmaxf(d[nt][1] + b1, 0.0f);
        float v2 = fmaxf(d[nt][2] + b0, 0.0f);
        float v3 = fmaxf(d[nt][3] + b1, 0.0f);
        *reinterpret_cast<float2*>(&C[(size_t)row0 * N + col]) = make_float2(v0, v1);
        *reinterpret_cast<float2*>(&C[(size_t)(row0 + 8) * N + col]) = make_float2(v2, v3);
    }
}

// ---------------- small GEMM (N=16), used once for wi3 -----------------------
template <int BM, int BN, int BK, int TM, int TN, int EPI>
__global__ void gemm_kernel(const float* __restrict__ A,
                            const float* __restrict__ W,
                            const float* __restrict__ bias,
                            float* __restrict__ C,
                            int K, int N) {
    constexpr int TX = BN / TN;
    constexpr int TY = BM / TM;
    static_assert(TX * TY == 256, "256 threads");
    constexpr int AS = BM + 4;
    __shared__ float As[BK][AS];
    __shared__ float Ws[BK][BN];

    int m0 = blockIdx.x * BM;
    int n0 = blockIdx.y * BN;
    int tid = threadIdx.x;
    int tx = tid % TX, ty = tid / TX;

    float acc[TM][TN];
#pragma unroll
    for (int i = 0; i < TM; i++)
#pragma unroll
        for (int j = 0; j < TN; j++) acc[i][j] = 0.0f;

    int am = tid >> 2;
    int aq = (tid & 3) * 4;

    for (int k0 = 0; k0 < K; k0 += BK) {
        {
            const float4 v = *reinterpret_cast<const float4*>(
                &A[(size_t)(m0 + am) * K + k0 + aq]);
            As[aq + 0][am] = v.x;
            As[aq + 1][am] = v.y;
            As[aq + 2][am] = v.z;
            As[aq + 3][am] = v.w;
        }
        for (int i = tid; i < BK * BN; i += 256) {
            int k = i / BN, n = i % BN;
            Ws[k][n] = W[(size_t)(k0 + k) * N + n0 + n];
        }
        __syncthreads();
#pragma unroll
        for (int kk = 0; kk < BK; kk++) {
            float a[TM], w[TN];
#pragma unroll
            for (int i = 0; i < TM; i++) a[i] = As[kk][ty * TM + i];
#pragma unroll
            for (int j = 0; j < TN; j++) w[j] = Ws[kk][tx * TN + j];
#pragma unroll
            for (int i = 0; i < TM; i++)
#pragma unroll
                for (int j = 0; j < TN; j++) acc[i][j] += a[i] * w[j];
        }
        __syncthreads();
    }
#pragma unroll
    for (int i = 0; i < TM; i++) {
        int m = m0 + ty * TM + i;
#pragma unroll
        for (int j = 0; j < TN; j++) {
            int n = n0 + tx * TN + j;
            float v = acc[i][j] + bias[n];
            if (EPI == 0) v = fmaxf(v, 0.0f);
            C[(size_t)m * N + n] = v;
        }
    }
}

// ---------------- fused wp2 -> wu1 -> wu2 -> state update (tensor core) ------
// 512 threads, 1 block/SM (128 KB dyn smem).
__global__ void __launch_bounds__(512, 1)
fused_step(const float* __restrict__ A,           // g_bufA (h1), row len 256
           const float* __restrict__ wp2, const float* __restrict__ bp2,
           const float* __restrict__ wu1, const float* __restrict__ bu1,
           const float* __restrict__ wu2, const float* __restrict__ bu2,
           const float* __restrict__ sstep,
           float* __restrict__ state) {
    extern __shared__ float dyn[];
    float* AsH = dyn + F_ASH;
    float* AsL = dyn + F_ASL;
    float* WsH = dyn + F_WSH;
    float* WsL = dyn + F_WSL;
    float* HsH = dyn + F_HSH;   // [128][APAD]
    float* HsL = dyn + F_HSL;
    float* bp2s = dyn + F_B1;
    float* bu1s = dyn + F_B2;
    float* bu2s = dyn + F_B3;

    int m0 = blockIdx.x * 64;
    int tid = threadIdx.x;
    int warp = tid >> 5, lane = tid & 31;
    int wm = warp >> 2, wn = warp & 3;
    int mb = 16 * wm, nbase = 32 * wn;
    int r = lane >> 2, cc = lane & 3;

    int am = tid >> 3;
    int aq = (tid & 7) * 2;
    int wk = tid >> 5;
    int wn4 = (tid & 31) * 4;

    if (tid < 128) { bp2s[tid] = bp2[tid]; bu1s[tid] = bu1[tid]; }
    if (tid < 16)  { bu2s[tid] = bu2[tid]; }

    const int ASTRIDE = 16 * APAD, WSTRIDE = 16 * WPAD;

    float d[4][4];
#pragma unroll
    for (int i = 0; i < 4; i++)
#pragma unroll
        for (int j = 0; j < 4; j++) d[i][j] = 0.0f;

    // ---- phase 1: h2 = relu(h1 @ wp2 + bp2), K=256 ----
    {
        float2 v = *reinterpret_cast<const float2*>(&A[(size_t)(m0 + am) * 256 + aq]);
        float h, l;
        split_tf32(v.x, h, l);
        AsH[aq * APAD + am] = h; AsL[aq * APAD + am] = l;
        split_tf32(v.y, h, l);
        AsH[(aq + 1) * APAD + am] = h; AsL[(aq + 1) * APAD + am] = l;

        float4 w = *reinterpret_cast<const float4*>(&wp2[(size_t)wk * 128 + wn4]);
        float4 wh, wl;
        split_tf32(w.x, wh.x, wl.x); split_tf32(w.y, wh.y, wl.y);
        split_tf32(w.z, wh.z, wl.z); split_tf32(w.w, wh.w, wl.w);
        *reinterpret_cast<float4*>(&WsH[wk * WPAD + wn4]) = wh;
        *reinterpret_cast<float4*>(&WsL[wk * WPAD + wn4]) = wl;
    }
    __syncthreads();

    int p = 0;
    for (int t = 0; t < 16; t++) {
        float2 pa;
        float4 pw;
        bool has = (t + 1 < 16);
        if (has) {
            int k0 = (t + 1) << 4;
            pa = *reinterpret_cast<const float2*>(&A[(size_t)(m0 + am) * 256 + k0 + aq]);
            pw = *reinterpret_cast<const float4*>(&wp2[(size_t)(k0 + wk) * 128 + wn4]);
        }
        const float* ash = AsH + p * ASTRIDE;
        const float* asl = AsL + p * ASTRIDE;
        const float* wsh = WsH + p * WSTRIDE;
        const float* wsl = WsL + p * WSTRIDE;
        warp_k8(d, ash, asl, wsh, wsl, 0, mb, nbase, r, cc);
        warp_k8(d, ash, asl, wsh, wsl, 8, mb, nbase, r, cc);
        if (has) {
            int q = p ^ 1;
            float h, l;
            split_tf32(pa.x, h, l);
            AsH[q * ASTRIDE + aq * APAD + am] = h; AsL[q * ASTRIDE + aq * APAD + am] = l;
            split_tf32(pa.y, h, l);
            AsH[q * ASTRIDE + (aq + 1) * APAD + am] = h; AsL[q * ASTRIDE + (aq + 1) * APAD + am] = l;
            float4 wh, wl;
            split_tf32(pw.x, wh.x, wl.x); split_tf32(pw.y, wh.y, wl.y);
            split_tf32(pw.z, wh.z, wl.z); split_tf32(pw.w, wh.w, wl.w);
            *reinterpret_cast<float4*>(&WsH[q * WSTRIDE + wk * WPAD + wn4]) = wh;
            *reinterpret_cast<float4*>(&WsL[q * WSTRIDE + wk * WPAD + wn4]) = wl;
        }
        __syncthreads();
        p ^= 1;
    }

    // epilogue 1: h2 -> HsH/HsL (transposed [n][m], tf32 split); stage wu1 tile 0
    {
        int row0 = mb + r;
#pragma unroll
        for (int nt = 0; nt < 4; nt++) {
            int col = nbase + 8 * nt + 2 * cc;
            float b0 = bp2s[col], b1 = bp2s[col + 1];
            float v0 = fmaxf(d[nt][0] + b0, 0.0f);
            float v1 = fmaxf(d[nt][1] + b1, 0.0f);
            float v2 = fmaxf(d[nt][2] + b0, 0.0f);
            float v3 = fmaxf(d[nt][3] + b1, 0.0f);
            float h, l;
            split_tf32(v0, h, l); HsH[col * APAD + row0] = h;       HsL[col * APAD + row0] = l;
            split_tf32(v1, h, l); HsH[(col + 1) * APAD + row0] = h; HsL[(col + 1) * APAD + row0] = l;
            split_tf32(v2, h, l); HsH[col * APAD + row0 + 8] = h;       HsL[col * APAD + row0 + 8] = l;
            split_tf32(v3, h, l); HsH[(col + 1) * APAD + row0 + 8] = h; HsL[(col + 1) * APAD + row0 + 8] = l;
        }
        float4 w = *reinterpret_cast<const float4*>(&wu1[(size_t)wk * 128 + wn4]);
        float4 wh, wl;
        split_tf32(w.x, wh.x, wl.x); split_tf32(w.y, wh.y, wl.y);
        split_tf32(w.z, wh.z, wl.z); split_tf32(w.w, wh.w, wl.w);
        *reinterpret_cast<float4*>(&WsH[wk * WPAD + wn4]) = wh;
        *reinterpret_cast<float4*>(&WsL[wk * WPAD + wn4]) = wl;
    }
    __syncthreads();

    // ---- phase 2: dh = relu(h2 @ wu1 + bu1), K=128, A resident in Hs ----
#pragma unroll
    for (int i = 0; i < 4; i++)
#pragma unroll
        for (int j = 0; j < 4; j++) d[i][j] = 0.0f;

    p = 0;
    for (int c = 0; c < 8; c++) {
        float4 pw;
        bool has = (c + 1 < 8);
        if (has) {
            int k0 = (c + 1) << 4;
            pw = *reinterpret_cast<const float4*>(&wu1[(size_t)(k0 + wk) * 128 + wn4]);
        }
        const float* ash = HsH + c * ASTRIDE;
        const float* asl = HsL + c * ASTRIDE;
        const float* wsh = WsH + p * WSTRIDE;
        const float* wsl = WsL + p * WSTRIDE;
        warp_k8(d, ash, asl, wsh, wsl, 0, mb, nbase, r, cc);
        warp_k8(d, ash, asl, wsh, wsl, 8, mb, nbase, r, cc);
        if (has) {
            int q = p ^ 1;
            float4 wh, wl;
            split_tf32(pw.x, wh.x, wl.x); split_tf32(pw.y, wh.y, wl.y);
            split_tf32(pw.z, wh.z, wl.z); split_tf32(pw.w, wh.w, wl.w);
            *reinterpret_cast<float4*>(&WsH[q * WSTRIDE + wk * WPAD + wn4]) = wh;
            *reinterpret_cast<float4*>(&WsL[q * WSTRIDE + wk * WPAD + wn4]) = wl;
        }
        __syncthreads();
        p ^= 1;
    }

    // epilogue 2: dh (full fp32) -> HsH transposed; stage wu2 flat into Ws
    {
        int row0 = mb + r;
#pragma unroll
        for (int nt = 0; nt < 4; nt++) {
            int col = nbase + 8 * nt + 2 * cc;
            float b0 = bu1s[col], b1 = bu1s[col + 1];
            HsH[col * APAD + row0]           = fmaxf(d[nt][0] + b0, 0.0f);
            HsH[(col + 1) * APAD + row0]     = fmaxf(d[nt][1] + b1, 0.0f);
            HsH[col * APAD + row0 + 8]       = fmaxf(d[nt][2] + b0, 0.0f);
            HsH[(col + 1) * APAD + row0 + 8] = fmaxf(d[nt][3] + b1, 0.0f);
        }
        int f = tid * 4;   // 2048 floats
        *reinterpret_cast<float4*>(&WsH[f]) = *reinterpret_cast<const float4*>(&wu2[f]);
    }
    __syncthreads();

    // ---- phase 3: delta = dh @ wu2 + bu2; state += step*delta (FFMA) ----
    {
        const float* wflat = WsH;
        int col = tid & 15;
        int rg  = tid >> 4;   // 0..31 -> rows rg*2, rg*2+1
        float acc0 = 0.0f, acc1 = 0.0f;
        for (int kk = 0; kk < 128; kk++) {
            float w = wflat[kk * 16 + col];
            float2 a2 = *reinterpret_cast<const float2*>(&HsH[kk * APAD + rg * 2]);
            acc0 += a2.x * w;
            acc1 += a2.y * w;
        }
        float stp = sstep[0];
        float bv = bu2s[col];
        int m = m0 + rg * 2;
        state[(size_t)m * SD + col]       += stp * (acc0 + bv);
        state[(size_t)(m + 1) * SD + col] += stp * (acc1 + bv);
    }
}

// ---------------- initial state build ----------------------------------------
__global__ void init_state_kernel(const float* __restrict__ sx,
                                  const float* __restrict__ sy,
                                  const float* __restrict__ doff) {
    int row = blockIdx.x * blockDim.x + threadIdx.x;
    if (row >= NROWS) return;
    int n = row % NP;
    const float* ini = g_init + (size_t)row * SD;
    float* st = g_state + (size_t)row * SD;
    st[0] = sx[n] + ini[0] * 0.15f;
    st[1] = sy[n] + ini[1] * 0.15f;
    st[2] = doff[0] + g_dep[row] * -2.0f;
#pragma unroll
    for (int i = 3; i < SD; i++) st[i] = ini[i];
}

// ---------------- fused kNN + pin gather (2 blocks per batch) ----------------
__global__ void __launch_bounds__(384) neighpin_kernel() {
    __shared__ float st[NP * SD];   // 24128 B
    int b = blockIdx.x >> 1;
    int half = blockIdx.x & 1;
    int t = threadIdx.x;

    const float4* gs = reinterpret_cast<const float4*>(g_state + (size_t)b * NP * SD);
    float4* s4 = reinterpret_cast<float4*>(st);
    for (int i = t; i < NP * SD / 4; i += 384) s4[i] = gs[i];
    __syncthreads();

    int pt = half * 189 + t;
    if (t >= 189 || pt >= NP) return;

    float bd[KNEI + 1];
    int bi[KNEI + 1];
#pragma unroll
    for (int i = 0; i <= KNEI; i++) { bd[i] = 3.4e38f; bi[i] = -1; }

    float x = st[pt * SD + 0], y = st[pt * SD + 1], z = st[pt * SD + 2];
    for (int j = 0; j < NP; j++) {
        float dx = x - st[j * SD + 0];
        float dy = y - st[j * SD + 1];
        float dz = z - st[j * SD + 2];
        float d2 = dx * dx + dy * dy + dz * dz;
        if (d2 < bd[KNEI]) {
            int p = KNEI;
            while (p > 0 && bd[p - 1] > d2) {
                bd[p] = bd[p - 1];
                bi[p] = bi[p - 1];
                p--;
            }
            bd[p] = d2;
            bi[p] = j;
        }
    }

    float4* p4 = reinterpret_cast<float4*>(g_pin + (size_t)(b * NP + pt) * PIN_DIM);
    const float4* self = reinterpret_cast<const float4*>(&st[pt * SD]);
#pragma unroll
    for (int q = 0; q < 4; q++) p4[q] = self[q];
#pragma unroll
    for (int k = 0; k < KNEI; k++) {
        const float4* nb = reinterpret_cast<const float4*>(&st[bi[k + 1] * SD]);
#pragma unroll
        for (int q = 0; q < 4; q++) p4[4 + k * 4 + q] = nb[q];
    }
}

// ---------------- postprocess ------------------------------------------------
__device__ __forceinline__ float sgnf(float x) {
    return (x > 0.0f) ? 1.0f : ((x < 0.0f) ? -1.0f : 0.0f);
}

__global__ void final_kernel(float* __restrict__ out) {
    int row = blockIdx.x * blockDim.x + threadIdx.x;
    if (row >= NROWS) return;
    const float* s = g_state + (size_t)row * SD;
    float o[14];
    o[0] = s[0]; o[1] = s[1]; o[2] = s[2];

#pragma unroll
    for (int i = 0; i < 3; i++) {
        float tv = fminf(fmaxf(s[3 + i], -10.0f), 20.0f) + 1.0f;
        float sp = log1pf(expf(tv));
        o[3 + i] = fminf(fmaxf(sp * 0.15f, 1e-6f), 2.0f);
    }

    const float eps = 1e-8f;
    float a1x = s[6], a1y = s[7], a1z = s[8];
    float a2x = s[9], a2y = s[10], a2z = s[11];
    float n1 = sqrtf(a1x * a1x + a1y * a1y + a1z * a1z) + eps;
    float b1x = a1x / n1, b1y = a1y / n1, b1z = a1z / n1;
    float dd = b1x * a2x + b1y * a2y + b1z * a2z;
    float pxv = a2x - dd * b1x, pyv = a2y - dd * b1y, pzv = a2z - dd * b1z;
    float n2 = sqrtf(pxv * pxv + pyv * pyv + pzv * pzv) + eps;
    float b2x = pxv / n2, b2y = pyv / n2, b2z = pzv / n2;
    float b3x = b1y * b2z - b1z * b2y;
    float b3y = b1z * b2x - b1x * b2z;
    float b3z = b1x * b2y - b1y * b2x;
    float m00 = b1x, m11 = b2y, m22 = b3z;
    float qw = 0.5f * sqrtf(fmaxf(1.0f + m00 + m11 + m22, 0.0f) + eps);
    float qx = 0.5f * sqrtf(fmaxf(1.0f + m00 - m11 - m22, 0.0f) + eps) * sgnf(b2z - b3y);
    float qy = 0.5f * sqrtf(fmaxf(1.0f - m00 + m11 - m22, 0.0f) + eps) * sgnf(b3x - b1z);
    float qz = 0.5f * sqrtf(fmaxf(1.0f - m00 - m11 + m22, 0.0f) + eps) * sgnf(b1y - b2x);
    float qn = sqrtf(qw * qw + qx * qx + qy * qy + qz * qz) + eps;
    o[6] = qw / qn; o[7] = qx / qn; o[8] = qy / qn; o[9] = qz / qn;

    o[10] = 1.0f / (1.0f + expf(-s[12]));
    o[11] = 1.0f / (1.0f + expf(-s[13]));
    o[12] = 1.0f / (1.0f + expf(-s[14]));
    o[13] = 1.0f / (1.0f + expf(-s[15]));

    float* op = out + (size_t)row * 14;
#pragma unroll
    for (int i = 0; i < 14; i++) op[i] = o[i];
}

// ---------------- launch ------------------------------------------------------
extern "C" void kernel_launch(void* const* d_in, const int* in_sizes, int n_in,
                              void* d_out, int out_size) {
    const float* feat  = (const float*)d_in[0];
    const float* depth = (const float*)d_in[1];
    const float* sx    = (const float*)d_in[2];
    const float* sy    = (const float*)d_in[3];
    const float* doff  = (const float*)d_in[4];
    const float* sstep = (const float*)d_in[5];
    const float* wi1 = (const float*)d_in[6];
    const float* bi1 = (const float*)d_in[7];
    const float* wi2 = (const float*)d_in[8];
    const float* bi2 = (const float*)d_in[9];
    const float* wi3 = (const float*)d_in[10];
    const float* bi3 = (const float*)d_in[11];
    const float* wp1 = (const float*)d_in[12];
    const float* bp1 = (const float*)d_in[13];
    const float* wp2 = (const float*)d_in[14];
    const float* bp2 = (const float*)d_in[15];
    const float* wu1 = (const float*)d_in[16];
    const float* bu1 = (const float*)d_in[17];
    const float* wu2 = (const float*)d_in[18];
    const float* bu2 = (const float*)d_in[19];

    cudaFuncSetAttribute(gemm_tc, cudaFuncAttributeMaxDynamicSharedMemorySize, G_TOTAL_B);
    cudaFuncSetAttribute(fused_step, cudaFuncAttributeMaxDynamicSharedMemorySize, F_TOTAL_B);

    void *pFs, *pA, *pB, *pInit, *pState, *pPin;
    cudaGetSymbolAddress(&pFs, g_Fs);
    cudaGetSymbolAddress(&pA, g_bufA);
    cudaGetSymbolAddress(&pB, g_bufB);
    cudaGetSymbolAddress(&pInit, g_init);
    cudaGetSymbolAddress(&pState, g_state);
    cudaGetSymbolAddress(&pPin, g_pin);
    float* Fs = (float*)pFs;
    float* bufA = (float*)pA;
    float* bufB = (float*)pB;
    float* initb = (float*)pInit;
    float* state = (float*)pState;
    float* pin = (float*)pPin;

    const int MB = NROWS / 64;  // 377

    // launches 0,1: sampling (launch #3 = gemm_tc wi2 for ncu)
    sample_feat_kernel<<<NROWS, 128>>>(feat, sx, sy);
    sample_depth_kernel<<<(NROWS + 127) / 128, 128>>>(depth, sx, sy);

    // launch 2: wi1 (K=384, N=256); launch 3: wi2 (K=256, N=128) <- profiled
    gemm_tc<<<dim3(MB, 2), 512, G_TOTAL_B>>>(Fs, wi1, bi1, bufA, CIN, H2X);
    gemm_tc<<<dim3(MB, 1), 512, G_TOTAL_B>>>(bufA, wi2, bi2, bufB, H2X, HID);
    gemm_kernel<64, 16, 16, 4, 1, 1><<<dim3(MB, 1), 256>>>(bufB, wi3, bi3, initb, HID, SD);

    init_state_kernel<<<(NROWS + 255) / 256, 256>>>(sx, sy, doff);

    for (int s = 0; s < NSTEPS; s++) {
        neighpin_kernel<<<BB * 2, 384>>>();
        gemm_tc<<<dim3(MB, 2), 512, G_TOTAL_B>>>(pin, wp1, bp1, bufA, PIN_DIM, H2X);
        fused_step<<<MB, 512, F_TOTAL_B>>>(bufA, wp2, bp2, wu1, bu1, wu2, bu2, sstep, state);
    }

    final_kernel<<<(NROWS + 255) / 256, 256>>>((float*)d_out);
}